// round 12
// baseline (speedup 1.0000x reference)
#include <cuda_runtime.h>
#include <cuda_fp16.h>
#include <cstdint>

#define NN    100000
#define FEAT  64
#define INC   128
#define EMAX  3400000
#define SB    256
#define NBLK1 ((NN + SB - 1) / SB)        // 391

// Scratch (device globals — no allocation allowed anywhere)
__device__ int   g_cnt[NN];
__device__ int   g_rowstart[NN];
__device__ int   g_cursor[NN];
__device__ int   g_bsum[NBLK1];
__device__ int   g_boff[NBLK1];
__device__ __align__(8) int2 g_csr[EMAX];                 // {src, bits(dinv[src])}
__device__ float g_dinv[NN];
__device__ __align__(16) __half g_Hh[(size_t)NN * FEAT];  // X @ (W1 W2), fp16
__device__ __align__(16) __half g_Th[(size_t)NN * FEAT];  // A_hat @ H, fp16
__device__ __align__(16) float  g_Wc[INC * FEAT];         // W1 @ W2
__device__ __align__(16) float  g_bW[FEAT];               // b1 @ W2

// ---------------------------------------------------------------------------
__global__ void k_zero(int n) {
    int i = blockIdx.x * blockDim.x + threadIdx.x;
    if (i < n) g_cnt[i] = 0;
}

__global__ void k_histo(const int* __restrict__ dst, int E) {
    int e = blockIdx.x * blockDim.x + threadIdx.x;
    if (e < E) {
        unsigned d = (unsigned)dst[e];
        if (d < NN) atomicAdd(&g_cnt[d], 1);
    }
}

// Level-1 scan: 256-thread blocks, warp-shuffle based.
__global__ void __launch_bounds__(SB) k_scan1(int n) {
    __shared__ int wsum[8];
    int i = blockIdx.x * SB + threadIdx.x;
    int lane = threadIdx.x & 31, w = threadIdx.x >> 5;
    int v = (i < n) ? g_cnt[i] : 0;
    int xv = v;
    #pragma unroll
    for (int off = 1; off < 32; off <<= 1) {
        int t = __shfl_up_sync(0xffffffffu, xv, off);
        if (lane >= off) xv += t;
    }
    if (lane == 31) wsum[w] = xv;
    __syncthreads();
    if (w == 0) {
        int s = (lane < 8) ? wsum[lane] : 0;
        #pragma unroll
        for (int off = 1; off < 8; off <<= 1) {
            int t = __shfl_up_sync(0xffffffffu, s, off);
            if (lane >= off) s += t;
        }
        if (lane < 8) wsum[lane] = s;
    }
    __syncthreads();
    int incl = xv + ((w > 0) ? wsum[w - 1] : 0);
    if (i < n) g_rowstart[i] = incl;
    if (threadIdx.x == SB - 1) g_bsum[blockIdx.x] = incl;
}

// Level-2: one 512-thread block scans the NBLK1 block totals (exclusive).
__global__ void __launch_bounds__(512) k_scan2() {
    __shared__ int sh[512];
    int t = threadIdx.x;
    int v = (t < NBLK1) ? g_bsum[t] : 0;
    sh[t] = v;
    __syncthreads();
    for (int off = 1; off < 512; off <<= 1) {
        int tv = (t >= off) ? sh[t - off] : 0;
        __syncthreads();
        sh[t] += tv;
        __syncthreads();
    }
    if (t < NBLK1) g_boff[t] = sh[t] - v;   // exclusive prefix
}

__global__ void k_scan3(int n) {
    int i = blockIdx.x * blockDim.x + threadIdx.x;
    if (i < n) {
        int c = g_cnt[i];
        int start = g_rowstart[i] - c + g_boff[i / SB];
        g_rowstart[i] = start;
        g_cursor[i]   = start;
        g_dinv[i]     = rsqrtf((float)(c + 1));   // + self-loop
    }
}

// Scatter with fused payload: {src, bits(dinv[src])}.
__global__ void k_scatter(const int* __restrict__ src, const int* __restrict__ dst,
                          int E) {
    int e = blockIdx.x * blockDim.x + threadIdx.x;
    if (e < E) {
        unsigned d = (unsigned)dst[e];
        unsigned s = (unsigned)src[e];
        if (d < NN && s < NN) {
            int pos = atomicAdd(&g_cursor[d], 1);
            if ((unsigned)pos < EMAX) {
                int2 p;
                p.x = (int)s;
                p.y = __float_as_int(g_dinv[s]);
                g_csr[pos] = p;
            }
        }
    }
}

// Wc row k = W1[k,:] @ W2 ; block 128 computes bW = b1 @ W2.
__global__ void __launch_bounds__(64) k_small(const float* __restrict__ W1,
                                              const float* __restrict__ b1,
                                              const float* __restrict__ W2) {
    __shared__ float sA[INC];
    int k = blockIdx.x;
    const float* arow = (k < INC) ? (W1 + k * INC) : b1;
    for (int i = threadIdx.x; i < INC; i += 64) sA[i] = arow[i];
    __syncthreads();
    int c = threadIdx.x;
    float acc = 0.f;
    #pragma unroll 16
    for (int j = 0; j < INC; j++) acc += sA[j] * W2[j * FEAT + c];
    if (k < INC) g_Wc[k * FEAT + c] = acc;
    else         g_bW[c] = acc;
}

// H = X @ Wc, output fp16. One warp per row; lane computes cols 2l, 2l+1.
__global__ void __launch_bounds__(256) k_gemm(const float* __restrict__ x, int n) {
    __shared__ float sW[INC * FEAT];   // 32 KB
    __shared__ float sx[8][INC];
    for (int i = threadIdx.x; i < INC * FEAT; i += blockDim.x) sW[i] = g_Wc[i];
    __syncthreads();

    int w = threadIdx.x >> 5, lane = threadIdx.x & 31;
    const float2* sW2 = reinterpret_cast<const float2*>(sW);
    for (int row = blockIdx.x * 8 + w; row < n; row += gridDim.x * 8) {
        float4 xv = reinterpret_cast<const float4*>(x + (size_t)row * INC)[lane];
        sx[w][lane * 4 + 0] = xv.x;
        sx[w][lane * 4 + 1] = xv.y;
        sx[w][lane * 4 + 2] = xv.z;
        sx[w][lane * 4 + 3] = xv.w;
        __syncwarp();

        float a0 = 0.f, a1 = 0.f;
        #pragma unroll
        for (int k = 0; k < INC; k++) {
            float xk = sx[w][k];
            float2 wv = sW2[k * 32 + lane];   // cols 2*lane, 2*lane+1
            a0 += xk * wv.x;
            a1 += xk * wv.y;
        }
        reinterpret_cast<__half2*>(g_Hh + (size_t)row * FEAT)[lane] =
            __floats2half2_rn(a0, a1);
        __syncwarp();
    }
}

// ---------------------------------------------------------------------------
__device__ __forceinline__ void unpack8(uint4 u, float f[8]) {
    float2 a = __half22float2(*reinterpret_cast<__half2*>(&u.x));
    float2 b = __half22float2(*reinterpret_cast<__half2*>(&u.y));
    float2 c = __half22float2(*reinterpret_cast<__half2*>(&u.z));
    float2 d = __half22float2(*reinterpret_cast<__half2*>(&u.w));
    f[0] = a.x; f[1] = a.y; f[2] = b.x; f[3] = b.y;
    f[4] = c.x; f[5] = c.y; f[6] = d.x; f[7] = d.y;
}

__device__ __forceinline__ uint4 pack8(const float f[8]) {
    uint4 u;
    __half2 h0 = __floats2half2_rn(f[0], f[1]);
    __half2 h1 = __floats2half2_rn(f[2], f[3]);
    __half2 h2 = __floats2half2_rn(f[4], f[5]);
    __half2 h3 = __floats2half2_rn(f[6], f[7]);
    u.x = *reinterpret_cast<unsigned*>(&h0);
    u.y = *reinterpret_cast<unsigned*>(&h1);
    u.z = *reinterpret_cast<unsigned*>(&h2);
    u.w = *reinterpret_cast<unsigned*>(&h3);
    return u;
}

__device__ __forceinline__ void clamp_row(int& beg, int& cnt) {
    if (beg < 0 || beg >= EMAX) { beg = 0; cnt = 0; }
    if (cnt < 0) cnt = 0;
    if (cnt > EMAX - beg) cnt = EMAX - beg;
}

__device__ __forceinline__ int safe_src(int s) {
    return ((unsigned)s < NN) ? s : 0;
}

// CSR propagation 1 (fp16 gather, fp32 accum): T = A_hat @ H.
// 8 lanes per row, each lane owns 8 features (one uint4 = 16 B).
__global__ void __launch_bounds__(256) k_prop1(int n) {
    int t = blockIdx.x * 256 + threadIdx.x;
    int row = t >> 3;
    if (row >= n) return;
    int li = t & 7;
    const uint4* H = reinterpret_cast<const uint4*>(g_Hh);   // 8 uint4 per row
    float dv = g_dinv[row];
    int beg = g_rowstart[row], cnt = g_cnt[row];
    clamp_row(beg, cnt);

    float acc[8], f[8];
    unpack8(H[(size_t)row * 8 + li], acc);
    float d2 = dv * dv;
    #pragma unroll
    for (int j = 0; j < 8; j++) acc[j] *= d2;

    int k = 0;
    for (; k + 4 <= cnt; k += 4) {
        int2 e0 = g_csr[beg + k + 0];
        int2 e1 = g_csr[beg + k + 1];
        int2 e2 = g_csr[beg + k + 2];
        int2 e3 = g_csr[beg + k + 3];
        int s0 = safe_src(e0.x), s1 = safe_src(e1.x);
        int s2 = safe_src(e2.x), s3 = safe_src(e3.x);
        float n0 = dv * __int_as_float(e0.y);
        float n1 = dv * __int_as_float(e1.y);
        float n2 = dv * __int_as_float(e2.y);
        float n3 = dv * __int_as_float(e3.y);
        uint4 u0 = H[(size_t)s0 * 8 + li];
        uint4 u1 = H[(size_t)s1 * 8 + li];
        uint4 u2 = H[(size_t)s2 * 8 + li];
        uint4 u3 = H[(size_t)s3 * 8 + li];
        unpack8(u0, f);
        #pragma unroll
        for (int j = 0; j < 8; j++) acc[j] += f[j] * n0;
        unpack8(u1, f);
        #pragma unroll
        for (int j = 0; j < 8; j++) acc[j] += f[j] * n1;
        unpack8(u2, f);
        #pragma unroll
        for (int j = 0; j < 8; j++) acc[j] += f[j] * n2;
        unpack8(u3, f);
        #pragma unroll
        for (int j = 0; j < 8; j++) acc[j] += f[j] * n3;
    }
    for (; k < cnt; k++) {
        int2 e = g_csr[beg + k];
        int s = safe_src(e.x);
        float nm = dv * __int_as_float(e.y);
        unpack8(H[(size_t)s * 8 + li], f);
        #pragma unroll
        for (int j = 0; j < 8; j++) acc[j] += f[j] * nm;
    }
    reinterpret_cast<uint4*>(g_Th)[(size_t)row * 8 + li] = pack8(acc);
}

// CSR propagation 2 + epilogue (fp16 gather, fp32 accum + fp32 out):
// out[d] = dinv^2*T[d] + sum nm*T[s] + (dinv^2 + sum nm)*bW + b2
__global__ void __launch_bounds__(256) k_prop2(const float* __restrict__ b2,
                                               float* __restrict__ out, int n) {
    int t = blockIdx.x * 256 + threadIdx.x;
    int row = t >> 3;
    if (row >= n) return;
    int li = t & 7;
    const uint4* T = reinterpret_cast<const uint4*>(g_Th);
    float dv = g_dinv[row];
    int beg = g_rowstart[row], cnt = g_cnt[row];
    clamp_row(beg, cnt);

    float acc[8], f[8];
    unpack8(T[(size_t)row * 8 + li], acc);
    float d2 = dv * dv;
    float sn = d2;                        // row sum of A_hat
    #pragma unroll
    for (int j = 0; j < 8; j++) acc[j] *= d2;

    int k = 0;
    for (; k + 4 <= cnt; k += 4) {
        int2 e0 = g_csr[beg + k + 0];
        int2 e1 = g_csr[beg + k + 1];
        int2 e2 = g_csr[beg + k + 2];
        int2 e3 = g_csr[beg + k + 3];
        int s0 = safe_src(e0.x), s1 = safe_src(e1.x);
        int s2 = safe_src(e2.x), s3 = safe_src(e3.x);
        float n0 = dv * __int_as_float(e0.y);
        float n1 = dv * __int_as_float(e1.y);
        float n2 = dv * __int_as_float(e2.y);
        float n3 = dv * __int_as_float(e3.y);
        uint4 u0 = T[(size_t)s0 * 8 + li];
        uint4 u1 = T[(size_t)s1 * 8 + li];
        uint4 u2 = T[(size_t)s2 * 8 + li];
        uint4 u3 = T[(size_t)s3 * 8 + li];
        sn += n0 + n1 + n2 + n3;
        unpack8(u0, f);
        #pragma unroll
        for (int j = 0; j < 8; j++) acc[j] += f[j] * n0;
        unpack8(u1, f);
        #pragma unroll
        for (int j = 0; j < 8; j++) acc[j] += f[j] * n1;
        unpack8(u2, f);
        #pragma unroll
        for (int j = 0; j < 8; j++) acc[j] += f[j] * n2;
        unpack8(u3, f);
        #pragma unroll
        for (int j = 0; j < 8; j++) acc[j] += f[j] * n3;
    }
    for (; k < cnt; k++) {
        int2 e = g_csr[beg + k];
        int s = safe_src(e.x);
        float nm = dv * __int_as_float(e.y);
        unpack8(T[(size_t)s * 8 + li], f);
        sn += nm;
        #pragma unroll
        for (int j = 0; j < 8; j++) acc[j] += f[j] * nm;
    }

    float4 bwa = reinterpret_cast<const float4*>(g_bW)[li * 2 + 0];
    float4 bwb = reinterpret_cast<const float4*>(g_bW)[li * 2 + 1];
    float4 b2a = reinterpret_cast<const float4*>(b2)[li * 2 + 0];
    float4 b2b = reinterpret_cast<const float4*>(b2)[li * 2 + 1];
    float4 oa, ob;
    oa.x = acc[0] + sn * bwa.x + b2a.x;
    oa.y = acc[1] + sn * bwa.y + b2a.y;
    oa.z = acc[2] + sn * bwa.z + b2a.z;
    oa.w = acc[3] + sn * bwa.w + b2a.w;
    ob.x = acc[4] + sn * bwb.x + b2b.x;
    ob.y = acc[5] + sn * bwb.y + b2b.y;
    ob.z = acc[6] + sn * bwb.z + b2b.z;
    ob.w = acc[7] + sn * bwb.w + b2b.w;
    float4* op = reinterpret_cast<float4*>(out + (size_t)row * FEAT + li * 8);
    op[0] = oa;
    op[1] = ob;
}

// ---------------------------------------------------------------------------
extern "C" void kernel_launch(void* const* d_in, const int* in_sizes, int n_in,
                              void* d_out, int out_size) {
    const float* x   = (const float*)d_in[0];
    const int*   ei  = (const int*)d_in[1];    // int64 downcast to int32 by harness
    const float* W1  = (const float*)d_in[2];
    const float* b1  = (const float*)d_in[3];
    const float* W2  = (const float*)d_in[4];
    const float* b2  = (const float*)d_in[5];
    float* out = (float*)d_out;

    int n = in_sizes[0] / INC;          // 100000
    int E = in_sizes[1] / 2;            // 3200000
    const int* srcp = ei;
    const int* dstp = ei + E;

    k_zero<<<(n + 255) / 256, 256>>>(n);
    k_histo<<<(E + 255) / 256, 256>>>(dstp, E);
    k_scan1<<<NBLK1, SB>>>(n);
    k_scan2<<<1, 512>>>();
    k_scan3<<<(n + 255) / 256, 256>>>(n);
    k_scatter<<<(E + 255) / 256, 256>>>(srcp, dstp, E);
    k_small<<<INC + 1, 64>>>(W1, b1, W2);
    k_gemm<<<(n + 7) / 8, 256>>>(x, n);
    int pgrid = (n * 8 + 255) / 256;
    k_prop1<<<pgrid, 256>>>(n);
    k_prop2<<<pgrid, 256>>>(b2, out, n);
}

// round 14
// speedup vs baseline: 1.0234x; 1.0234x over previous
#include <cuda_runtime.h>
#include <cuda_fp16.h>
#include <cstdint>

#define NN    100000
#define FEAT  64
#define INC   128
#define EMAX  3400000
#define SB    256
#define NBLK1 ((NN + SB - 1) / SB)        // 391

// Scratch (device globals — no allocation allowed anywhere)
__device__ int   g_cnt[NN];
__device__ int   g_rowstart[NN];
__device__ int   g_cursor[NN];
__device__ int   g_bsum[NBLK1];
__device__ int   g_boff[NBLK1];
__device__ int   g_csr_src[EMAX];
__device__ float g_dinv[NN];
__device__ __align__(16) __half g_Hh[(size_t)NN * FEAT];  // X @ (W1 W2), fp16
__device__ __align__(16) __half g_Th[(size_t)NN * FEAT];  // A_hat @ H, fp16
__device__ __align__(16) float  g_Wc[INC * FEAT];         // W1 @ W2
__device__ __align__(16) float  g_bW[FEAT];               // b1 @ W2

// ---------------------------------------------------------------------------
__global__ void k_zero(int n) {
    int i = blockIdx.x * blockDim.x + threadIdx.x;
    if (i < n) g_cnt[i] = 0;
}

__global__ void k_histo(const int* __restrict__ dst, int E) {
    int e = blockIdx.x * blockDim.x + threadIdx.x;
    if (e < E) {
        unsigned d = (unsigned)dst[e];
        if (d < NN) atomicAdd(&g_cnt[d], 1);
    }
}

// Level-1 scan: 256-thread blocks, warp-shuffle based.
__global__ void __launch_bounds__(SB) k_scan1(int n) {
    __shared__ int wsum[8];
    int i = blockIdx.x * SB + threadIdx.x;
    int lane = threadIdx.x & 31, w = threadIdx.x >> 5;
    int v = (i < n) ? g_cnt[i] : 0;
    int xv = v;
    #pragma unroll
    for (int off = 1; off < 32; off <<= 1) {
        int t = __shfl_up_sync(0xffffffffu, xv, off);
        if (lane >= off) xv += t;
    }
    if (lane == 31) wsum[w] = xv;
    __syncthreads();
    if (w == 0) {
        int s = (lane < 8) ? wsum[lane] : 0;
        #pragma unroll
        for (int off = 1; off < 8; off <<= 1) {
            int t = __shfl_up_sync(0xffffffffu, s, off);
            if (lane >= off) s += t;
        }
        if (lane < 8) wsum[lane] = s;
    }
    __syncthreads();
    int incl = xv + ((w > 0) ? wsum[w - 1] : 0);
    if (i < n) g_rowstart[i] = incl;
    if (threadIdx.x == SB - 1) g_bsum[blockIdx.x] = incl;
}

// Level-2: one 512-thread block, shuffle-based exclusive scan of NBLK1 totals.
__global__ void __launch_bounds__(512) k_scan2() {
    __shared__ int wsum[16];
    int t = threadIdx.x;
    int lane = t & 31, w = t >> 5;
    int v = (t < NBLK1) ? g_bsum[t] : 0;
    int xv = v;
    #pragma unroll
    for (int off = 1; off < 32; off <<= 1) {
        int s = __shfl_up_sync(0xffffffffu, xv, off);
        if (lane >= off) xv += s;
    }
    if (lane == 31) wsum[w] = xv;
    __syncthreads();
    if (w == 0) {
        int s = (lane < 16) ? wsum[lane] : 0;
        #pragma unroll
        for (int off = 1; off < 16; off <<= 1) {
            int u = __shfl_up_sync(0xffffffffu, s, off);
            if (lane >= off) s += u;
        }
        if (lane < 16) wsum[lane] = s;
    }
    __syncthreads();
    int incl = xv + ((w > 0) ? wsum[w - 1] : 0);
    if (t < NBLK1) g_boff[t] = incl - v;   // exclusive prefix
}

__global__ void k_scan3(int n) {
    int i = blockIdx.x * blockDim.x + threadIdx.x;
    if (i < n) {
        int c = g_cnt[i];
        int start = g_rowstart[i] - c + g_boff[i / SB];
        g_rowstart[i] = start;
        g_cursor[i]   = start;
        g_dinv[i]     = rsqrtf((float)(c + 1));   // + self-loop
    }
}

__global__ void k_scatter(const int* __restrict__ src, const int* __restrict__ dst,
                          int E) {
    int e = blockIdx.x * blockDim.x + threadIdx.x;
    if (e < E) {
        unsigned d = (unsigned)dst[e];
        unsigned s = (unsigned)src[e];
        if (d < NN && s < NN) {
            int pos = atomicAdd(&g_cursor[d], 1);
            if ((unsigned)pos < EMAX) g_csr_src[pos] = (int)s;  // defensive
        }
    }
}

// Wc row k = W1[k,:] @ W2 ; block 128 computes bW = b1 @ W2.
__global__ void __launch_bounds__(64) k_small(const float* __restrict__ W1,
                                              const float* __restrict__ b1,
                                              const float* __restrict__ W2) {
    __shared__ float sA[INC];
    int k = blockIdx.x;
    const float* arow = (k < INC) ? (W1 + k * INC) : b1;
    for (int i = threadIdx.x; i < INC; i += 64) sA[i] = arow[i];
    __syncthreads();
    int c = threadIdx.x;
    float acc = 0.f;
    #pragma unroll 16
    for (int j = 0; j < INC; j++) acc += sA[j] * W2[j * FEAT + c];
    if (k < INC) g_Wc[k * FEAT + c] = acc;
    else         g_bW[c] = acc;
}

// H = X @ Wc, output fp16. One warp per row; lane computes cols 2l, 2l+1.
__global__ void __launch_bounds__(256) k_gemm(const float* __restrict__ x, int n) {
    __shared__ float sW[INC * FEAT];   // 32 KB
    __shared__ float sx[8][INC];
    for (int i = threadIdx.x; i < INC * FEAT; i += blockDim.x) sW[i] = g_Wc[i];
    __syncthreads();

    int w = threadIdx.x >> 5, lane = threadIdx.x & 31;
    const float2* sW2 = reinterpret_cast<const float2*>(sW);
    for (int row = blockIdx.x * 8 + w; row < n; row += gridDim.x * 8) {
        float4 xv = reinterpret_cast<const float4*>(x + (size_t)row * INC)[lane];
        sx[w][lane * 4 + 0] = xv.x;
        sx[w][lane * 4 + 1] = xv.y;
        sx[w][lane * 4 + 2] = xv.z;
        sx[w][lane * 4 + 3] = xv.w;
        __syncwarp();

        float a0 = 0.f, a1 = 0.f;
        #pragma unroll
        for (int k = 0; k < INC; k++) {
            float xk = sx[w][k];
            float2 wv = sW2[k * 32 + lane];   // cols 2*lane, 2*lane+1
            a0 += xk * wv.x;
            a1 += xk * wv.y;
        }
        reinterpret_cast<__half2*>(g_Hh + (size_t)row * FEAT)[lane] =
            __floats2half2_rn(a0, a1);
        __syncwarp();
    }
}

// ---------------------------------------------------------------------------
__device__ __forceinline__ void unpack8(uint4 u, float f[8]) {
    float2 a = __half22float2(*reinterpret_cast<__half2*>(&u.x));
    float2 b = __half22float2(*reinterpret_cast<__half2*>(&u.y));
    float2 c = __half22float2(*reinterpret_cast<__half2*>(&u.z));
    float2 d = __half22float2(*reinterpret_cast<__half2*>(&u.w));
    f[0] = a.x; f[1] = a.y; f[2] = b.x; f[3] = b.y;
    f[4] = c.x; f[5] = c.y; f[6] = d.x; f[7] = d.y;
}

__device__ __forceinline__ uint4 pack8(const float f[8]) {
    uint4 u;
    __half2 h0 = __floats2half2_rn(f[0], f[1]);
    __half2 h1 = __floats2half2_rn(f[2], f[3]);
    __half2 h2 = __floats2half2_rn(f[4], f[5]);
    __half2 h3 = __floats2half2_rn(f[6], f[7]);
    u.x = *reinterpret_cast<unsigned*>(&h0);
    u.y = *reinterpret_cast<unsigned*>(&h1);
    u.z = *reinterpret_cast<unsigned*>(&h2);
    u.w = *reinterpret_cast<unsigned*>(&h3);
    return u;
}

__device__ __forceinline__ void clamp_row(int& beg, int& cnt) {
    if (beg < 0 || beg >= EMAX) { beg = 0; cnt = 0; }
    if (cnt < 0) cnt = 0;
    if (cnt > EMAX - beg) cnt = EMAX - beg;
}

__device__ __forceinline__ int safe_src(int s) {
    return ((unsigned)s < NN) ? s : 0;
}

// CSR propagation 1 (fp16 gather, fp32 accum): T = A_hat @ H.
// 8 lanes per row, each lane owns 8 features (one uint4 = 16 B).
// Edge loop unrolled x8: index batch -> norm batch -> gather batch -> FMA.
__global__ void __launch_bounds__(256) k_prop1(int n) {
    int t = blockIdx.x * 256 + threadIdx.x;
    int row = t >> 3;
    if (row >= n) return;
    int li = t & 7;
    const uint4* H = reinterpret_cast<const uint4*>(g_Hh);   // 8 uint4 per row
    float dv = g_dinv[row];
    int beg = g_rowstart[row], cnt = g_cnt[row];
    clamp_row(beg, cnt);

    float acc[8], f[8];
    unpack8(H[(size_t)row * 8 + li], acc);
    float d2 = dv * dv;
    #pragma unroll
    for (int j = 0; j < 8; j++) acc[j] *= d2;

    int k = 0;
    for (; k + 8 <= cnt; k += 8) {
        int   ss[8];
        float nm[8];
        uint4 uu[8];
        #pragma unroll
        for (int q = 0; q < 8; q++) ss[q] = safe_src(g_csr_src[beg + k + q]);
        #pragma unroll
        for (int q = 0; q < 8; q++) nm[q] = dv * g_dinv[ss[q]];
        #pragma unroll
        for (int q = 0; q < 8; q++) uu[q] = H[(size_t)ss[q] * 8 + li];
        #pragma unroll
        for (int q = 0; q < 8; q++) {
            unpack8(uu[q], f);
            #pragma unroll
            for (int j = 0; j < 8; j++) acc[j] += f[j] * nm[q];
        }
    }
    for (; k < cnt; k++) {
        int s = safe_src(g_csr_src[beg + k]);
        float nm = dv * g_dinv[s];
        unpack8(H[(size_t)s * 8 + li], f);
        #pragma unroll
        for (int j = 0; j < 8; j++) acc[j] += f[j] * nm;
    }
    reinterpret_cast<uint4*>(g_Th)[(size_t)row * 8 + li] = pack8(acc);
}

// CSR propagation 2 + epilogue (fp16 gather, fp32 accum + fp32 out):
// out[d] = dinv^2*T[d] + sum nm*T[s] + (dinv^2 + sum nm)*bW + b2
__global__ void __launch_bounds__(256) k_prop2(const float* __restrict__ b2,
                                               float* __restrict__ out, int n) {
    int t = blockIdx.x * 256 + threadIdx.x;
    int row = t >> 3;
    if (row >= n) return;
    int li = t & 7;
    const uint4* T = reinterpret_cast<const uint4*>(g_Th);
    float dv = g_dinv[row];
    int beg = g_rowstart[row], cnt = g_cnt[row];
    clamp_row(beg, cnt);

    float acc[8], f[8];
    unpack8(T[(size_t)row * 8 + li], acc);
    float d2 = dv * dv;
    float sn = d2;                        // row sum of A_hat
    #pragma unroll
    for (int j = 0; j < 8; j++) acc[j] *= d2;

    int k = 0;
    for (; k + 8 <= cnt; k += 8) {
        int   ss[8];
        float nm[8];
        uint4 uu[8];
        #pragma unroll
        for (int q = 0; q < 8; q++) ss[q] = safe_src(g_csr_src[beg + k + q]);
        #pragma unroll
        for (int q = 0; q < 8; q++) nm[q] = dv * g_dinv[ss[q]];
        #pragma unroll
        for (int q = 0; q < 8; q++) uu[q] = T[(size_t)ss[q] * 8 + li];
        #pragma unroll
        for (int q = 0; q < 8; q++) {
            sn += nm[q];
            unpack8(uu[q], f);
            #pragma unroll
            for (int j = 0; j < 8; j++) acc[j] += f[j] * nm[q];
        }
    }
    for (; k < cnt; k++) {
        int s = safe_src(g_csr_src[beg + k]);
        float nm = dv * g_dinv[s];
        unpack8(T[(size_t)s * 8 + li], f);
        sn += nm;
        #pragma unroll
        for (int j = 0; j < 8; j++) acc[j] += f[j] * nm;
    }

    float4 bwa = reinterpret_cast<const float4*>(g_bW)[li * 2 + 0];
    float4 bwb = reinterpret_cast<const float4*>(g_bW)[li * 2 + 1];
    float4 b2a = reinterpret_cast<const float4*>(b2)[li * 2 + 0];
    float4 b2b = reinterpret_cast<const float4*>(b2)[li * 2 + 1];
    float4 oa, ob;
    oa.x = acc[0] + sn * bwa.x + b2a.x;
    oa.y = acc[1] + sn * bwa.y + b2a.y;
    oa.z = acc[2] + sn * bwa.z + b2a.z;
    oa.w = acc[3] + sn * bwa.w + b2a.w;
    ob.x = acc[4] + sn * bwb.x + b2b.x;
    ob.y = acc[5] + sn * bwb.y + b2b.y;
    ob.z = acc[6] + sn * bwb.z + b2b.z;
    ob.w = acc[7] + sn * bwb.w + b2b.w;
    float4* op = reinterpret_cast<float4*>(out + (size_t)row * FEAT + li * 8);
    op[0] = oa;
    op[1] = ob;
}

// ---------------------------------------------------------------------------
extern "C" void kernel_launch(void* const* d_in, const int* in_sizes, int n_in,
                              void* d_out, int out_size) {
    const float* x   = (const float*)d_in[0];
    const int*   ei  = (const int*)d_in[1];    // int64 downcast to int32 by harness
    const float* W1  = (const float*)d_in[2];
    const float* b1  = (const float*)d_in[3];
    const float* W2  = (const float*)d_in[4];
    const float* b2  = (const float*)d_in[5];
    float* out = (float*)d_out;

    int n = in_sizes[0] / INC;          // 100000
    int E = in_sizes[1] / 2;            // 3200000
    const int* srcp = ei;
    const int* dstp = ei + E;

    k_zero<<<(n + 255) / 256, 256>>>(n);
    k_histo<<<(E + 255) / 256, 256>>>(dstp, E);
    k_scan1<<<NBLK1, SB>>>(n);
    k_scan2<<<1, 512>>>();
    k_scan3<<<(n + 255) / 256, 256>>>(n);
    k_scatter<<<(E + 255) / 256, 256>>>(srcp, dstp, E);
    k_small<<<INC + 1, 64>>>(W1, b1, W2);
    k_gemm<<<(n + 7) / 8, 256>>>(x, n);
    int pgrid = (n * 8 + 255) / 256;
    k_prop1<<<pgrid, 256>>>(n);
    k_prop2<<<pgrid, 256>>>(b2, out, n);
}

// round 17
// speedup vs baseline: 1.0554x; 1.0313x over previous
#include <cuda_runtime.h>
#include <cuda_fp16.h>
#include <cstdint>

#define NN    100000
#define FEAT  64
#define INC   128
#define EMAX  3400000
#define SB    256
#define NBLK1 ((NN + SB - 1) / SB)        // 391

// Scratch (device globals — no allocation allowed anywhere)
__device__ int   g_cnt[NN];
__device__ int   g_rowstart[NN];
__device__ int   g_cursor[NN];
__device__ int   g_bsum[NBLK1];
__device__ int   g_boff[NBLK1];
__device__ int   g_csr_src[EMAX];
__device__ float g_dinv[NN];
__device__ __align__(16) __half g_Hh[(size_t)NN * FEAT];  // X @ (W1 W2), fp16
__device__ __align__(16) __half g_Th[(size_t)NN * FEAT];  // A_hat @ H, fp16
__device__ __align__(16) float  g_Wc[INC * FEAT];         // W1 @ W2
__device__ __align__(16) float  g_bW[FEAT];               // b1 @ W2

// ---------------------------------------------------------------------------
// Fused kernel A: blocks [0,nzb) zero g_cnt ; blocks [nzb,..) compute Wc/bW.
// Small part: each block handles 4 rows of [W1;b1] @ W2 (64 threads per row).
__global__ void __launch_bounds__(256) kA(const float* __restrict__ W1,
                                          const float* __restrict__ b1,
                                          const float* __restrict__ W2,
                                          int n, int nzb) {
    if ((int)blockIdx.x < nzb) {
        int i = blockIdx.x * 256 + threadIdx.x;
        if (i < n) g_cnt[i] = 0;
    } else {
        __shared__ float sA[4][INC];
        int rloc = threadIdx.x >> 6;
        int c    = threadIdx.x & 63;
        int kb   = ((int)blockIdx.x - nzb) * 4 + rloc;
        if (kb <= INC) {
            const float* arow = (kb < INC) ? (W1 + kb * INC) : b1;
            sA[rloc][c]      = arow[c];
            sA[rloc][c + 64] = arow[c + 64];
        }
        __syncthreads();
        if (kb <= INC) {
            float acc = 0.f;
            #pragma unroll 16
            for (int j = 0; j < INC; j++) acc += sA[rloc][j] * W2[j * FEAT + c];
            if (kb < INC) g_Wc[kb * FEAT + c] = acc;
            else          g_bW[c] = acc;
        }
    }
}

// Fused kernel B: parity-interleaved histogram + GEMM for co-residency.
// even blocks: histo over dst ; odd blocks: H = X @ Wc (fp16 out).
__global__ void __launch_bounds__(256) kB(const int* __restrict__ dst, int E,
                                          const float* __restrict__ x, int n,
                                          int nhb, int ngb) {
    __shared__ float sW[INC * FEAT];   // 32 KB
    __shared__ float sx[8][INC];       //  4 KB
    int sub = blockIdx.x >> 1;
    if ((blockIdx.x & 1) == 0) {
        // histogram role
        if (sub < nhb) {
            int e = sub * 256 + threadIdx.x;
            if (e < E) {
                unsigned d = (unsigned)dst[e];
                if (d < NN) atomicAdd(&g_cnt[d], 1);
            }
        }
    } else {
        // GEMM role
        if (sub < ngb) {
            for (int i = threadIdx.x; i < INC * FEAT; i += 256) sW[i] = g_Wc[i];
            __syncthreads();
            int w = threadIdx.x >> 5, lane = threadIdx.x & 31;
            const float2* sW2 = reinterpret_cast<const float2*>(sW);
            int row = sub * 8 + w;
            if (row < n) {
                float4 xv = reinterpret_cast<const float4*>(x + (size_t)row * INC)[lane];
                sx[w][lane * 4 + 0] = xv.x;
                sx[w][lane * 4 + 1] = xv.y;
                sx[w][lane * 4 + 2] = xv.z;
                sx[w][lane * 4 + 3] = xv.w;
                __syncwarp();
                float a0 = 0.f, a1 = 0.f;
                #pragma unroll
                for (int k = 0; k < INC; k++) {
                    float xk = sx[w][k];
                    float2 wv = sW2[k * 32 + lane];   // cols 2*lane, 2*lane+1
                    a0 += xk * wv.x;
                    a1 += xk * wv.y;
                }
                reinterpret_cast<__half2*>(g_Hh + (size_t)row * FEAT)[lane] =
                    __floats2half2_rn(a0, a1);
            }
        }
    }
}

// Level-1 scan: 256-thread blocks, warp-shuffle based.
__global__ void __launch_bounds__(SB) k_scan1(int n) {
    __shared__ int wsum[8];
    int i = blockIdx.x * SB + threadIdx.x;
    int lane = threadIdx.x & 31, w = threadIdx.x >> 5;
    int v = (i < n) ? g_cnt[i] : 0;
    int xv = v;
    #pragma unroll
    for (int off = 1; off < 32; off <<= 1) {
        int t = __shfl_up_sync(0xffffffffu, xv, off);
        if (lane >= off) xv += t;
    }
    if (lane == 31) wsum[w] = xv;
    __syncthreads();
    if (w == 0) {
        int s = (lane < 8) ? wsum[lane] : 0;
        #pragma unroll
        for (int off = 1; off < 8; off <<= 1) {
            int t = __shfl_up_sync(0xffffffffu, s, off);
            if (lane >= off) s += t;
        }
        if (lane < 8) wsum[lane] = s;
    }
    __syncthreads();
    int incl = xv + ((w > 0) ? wsum[w - 1] : 0);
    if (i < n) g_rowstart[i] = incl;
    if (threadIdx.x == SB - 1) g_bsum[blockIdx.x] = incl;
}

// Level-2: one 512-thread block, shuffle-based exclusive scan of NBLK1 totals.
__global__ void __launch_bounds__(512) k_scan2() {
    __shared__ int wsum[16];
    int t = threadIdx.x;
    int lane = t & 31, w = t >> 5;
    int v = (t < NBLK1) ? g_bsum[t] : 0;
    int xv = v;
    #pragma unroll
    for (int off = 1; off < 32; off <<= 1) {
        int s = __shfl_up_sync(0xffffffffu, xv, off);
        if (lane >= off) xv += s;
    }
    if (lane == 31) wsum[w] = xv;
    __syncthreads();
    if (w == 0) {
        int s = (lane < 16) ? wsum[lane] : 0;
        #pragma unroll
        for (int off = 1; off < 16; off <<= 1) {
            int u = __shfl_up_sync(0xffffffffu, s, off);
            if (lane >= off) s += u;
        }
        if (lane < 16) wsum[lane] = s;
    }
    __syncthreads();
    int incl = xv + ((w > 0) ? wsum[w - 1] : 0);
    if (t < NBLK1) g_boff[t] = incl - v;   // exclusive prefix
}

__global__ void k_scan3(int n) {
    int i = blockIdx.x * blockDim.x + threadIdx.x;
    if (i < n) {
        int c = g_cnt[i];
        int start = g_rowstart[i] - c + g_boff[i / SB];
        g_rowstart[i] = start;
        g_cursor[i]   = start;
        g_dinv[i]     = rsqrtf((float)(c + 1));   // + self-loop
    }
}

__global__ void k_scatter(const int* __restrict__ src, const int* __restrict__ dst,
                          int E) {
    int e = blockIdx.x * blockDim.x + threadIdx.x;
    if (e < E) {
        unsigned d = (unsigned)dst[e];
        unsigned s = (unsigned)src[e];
        if (d < NN && s < NN) {
            int pos = atomicAdd(&g_cursor[d], 1);
            if ((unsigned)pos < EMAX) g_csr_src[pos] = (int)s;  // defensive
        }
    }
}

// ---------------------------------------------------------------------------
__device__ __forceinline__ void unpack8(uint4 u, float f[8]) {
    float2 a = __half22float2(*reinterpret_cast<__half2*>(&u.x));
    float2 b = __half22float2(*reinterpret_cast<__half2*>(&u.y));
    float2 c = __half22float2(*reinterpret_cast<__half2*>(&u.z));
    float2 d = __half22float2(*reinterpret_cast<__half2*>(&u.w));
    f[0] = a.x; f[1] = a.y; f[2] = b.x; f[3] = b.y;
    f[4] = c.x; f[5] = c.y; f[6] = d.x; f[7] = d.y;
}

__device__ __forceinline__ uint4 pack8(const float f[8]) {
    uint4 u;
    __half2 h0 = __floats2half2_rn(f[0], f[1]);
    __half2 h1 = __floats2half2_rn(f[2], f[3]);
    __half2 h2 = __floats2half2_rn(f[4], f[5]);
    __half2 h3 = __floats2half2_rn(f[6], f[7]);
    u.x = *reinterpret_cast<unsigned*>(&h0);
    u.y = *reinterpret_cast<unsigned*>(&h1);
    u.z = *reinterpret_cast<unsigned*>(&h2);
    u.w = *reinterpret_cast<unsigned*>(&h3);
    return u;
}

__device__ __forceinline__ void clamp_row(int& beg, int& cnt) {
    if (beg < 0 || beg >= EMAX) { beg = 0; cnt = 0; }
    if (cnt < 0) cnt = 0;
    if (cnt > EMAX - beg) cnt = EMAX - beg;
}

__device__ __forceinline__ int safe_src(int s) {
    return ((unsigned)s < NN) ? s : 0;
}

// CSR propagation 1 (fp16 gather, fp32 accum): T = A_hat @ H.
// 8 lanes per row, each lane owns 8 features (one uint4 = 16 B).
__global__ void __launch_bounds__(256) k_prop1(int n) {
    int t = blockIdx.x * 256 + threadIdx.x;
    int row = t >> 3;
    if (row >= n) return;
    int li = t & 7;
    const uint4* H = reinterpret_cast<const uint4*>(g_Hh);   // 8 uint4 per row
    float dv = g_dinv[row];
    int beg = g_rowstart[row], cnt = g_cnt[row];
    clamp_row(beg, cnt);

    float acc[8], f[8];
    unpack8(H[(size_t)row * 8 + li], acc);
    float d2 = dv * dv;
    #pragma unroll
    for (int j = 0; j < 8; j++) acc[j] *= d2;

    int k = 0;
    for (; k + 4 <= cnt; k += 4) {
        int s0 = safe_src(g_csr_src[beg + k + 0]);
        int s1 = safe_src(g_csr_src[beg + k + 1]);
        int s2 = safe_src(g_csr_src[beg + k + 2]);
        int s3 = safe_src(g_csr_src[beg + k + 3]);
        float n0 = dv * g_dinv[s0], n1 = dv * g_dinv[s1];
        float n2 = dv * g_dinv[s2], n3 = dv * g_dinv[s3];
        uint4 u0 = H[(size_t)s0 * 8 + li];
        uint4 u1 = H[(size_t)s1 * 8 + li];
        uint4 u2 = H[(size_t)s2 * 8 + li];
        uint4 u3 = H[(size_t)s3 * 8 + li];
        unpack8(u0, f);
        #pragma unroll
        for (int j = 0; j < 8; j++) acc[j] += f[j] * n0;
        unpack8(u1, f);
        #pragma unroll
        for (int j = 0; j < 8; j++) acc[j] += f[j] * n1;
        unpack8(u2, f);
        #pragma unroll
        for (int j = 0; j < 8; j++) acc[j] += f[j] * n2;
        unpack8(u3, f);
        #pragma unroll
        for (int j = 0; j < 8; j++) acc[j] += f[j] * n3;
    }
    for (; k < cnt; k++) {
        int s = safe_src(g_csr_src[beg + k]);
        float nm = dv * g_dinv[s];
        unpack8(H[(size_t)s * 8 + li], f);
        #pragma unroll
        for (int j = 0; j < 8; j++) acc[j] += f[j] * nm;
    }
    reinterpret_cast<uint4*>(g_Th)[(size_t)row * 8 + li] = pack8(acc);
}

// CSR propagation 2 + epilogue (fp16 gather, fp32 accum + fp32 out):
// out[d] = dinv^2*T[d] + sum nm*T[s] + (dinv^2 + sum nm)*bW + b2
__global__ void __launch_bounds__(256) k_prop2(const float* __restrict__ b2,
                                               float* __restrict__ out, int n) {
    int t = blockIdx.x * 256 + threadIdx.x;
    int row = t >> 3;
    if (row >= n) return;
    int li = t & 7;
    const uint4* T = reinterpret_cast<const uint4*>(g_Th);
    float dv = g_dinv[row];
    int beg = g_rowstart[row], cnt = g_cnt[row];
    clamp_row(beg, cnt);

    float acc[8], f[8];
    unpack8(T[(size_t)row * 8 + li], acc);
    float d2 = dv * dv;
    float sn = d2;                        // row sum of A_hat
    #pragma unroll
    for (int j = 0; j < 8; j++) acc[j] *= d2;

    int k = 0;
    for (; k + 4 <= cnt; k += 4) {
        int s0 = safe_src(g_csr_src[beg + k + 0]);
        int s1 = safe_src(g_csr_src[beg + k + 1]);
        int s2 = safe_src(g_csr_src[beg + k + 2]);
        int s3 = safe_src(g_csr_src[beg + k + 3]);
        float n0 = dv * g_dinv[s0], n1 = dv * g_dinv[s1];
        float n2 = dv * g_dinv[s2], n3 = dv * g_dinv[s3];
        uint4 u0 = T[(size_t)s0 * 8 + li];
        uint4 u1 = T[(size_t)s1 * 8 + li];
        uint4 u2 = T[(size_t)s2 * 8 + li];
        uint4 u3 = T[(size_t)s3 * 8 + li];
        sn += n0 + n1 + n2 + n3;
        unpack8(u0, f);
        #pragma unroll
        for (int j = 0; j < 8; j++) acc[j] += f[j] * n0;
        unpack8(u1, f);
        #pragma unroll
        for (int j = 0; j < 8; j++) acc[j] += f[j] * n1;
        unpack8(u2, f);
        #pragma unroll
        for (int j = 0; j < 8; j++) acc[j] += f[j] * n2;
        unpack8(u3, f);
        #pragma unroll
        for (int j = 0; j < 8; j++) acc[j] += f[j] * n3;
    }
    for (; k < cnt; k++) {
        int s = safe_src(g_csr_src[beg + k]);
        float nm = dv * g_dinv[s];
        unpack8(T[(size_t)s * 8 + li], f);
        sn += nm;
        #pragma unroll
        for (int j = 0; j < 8; j++) acc[j] += f[j] * nm;
    }

    float4 bwa = reinterpret_cast<const float4*>(g_bW)[li * 2 + 0];
    float4 bwb = reinterpret_cast<const float4*>(g_bW)[li * 2 + 1];
    float4 b2a = reinterpret_cast<const float4*>(b2)[li * 2 + 0];
    float4 b2b = reinterpret_cast<const float4*>(b2)[li * 2 + 1];
    float4 oa, ob;
    oa.x = acc[0] + sn * bwa.x + b2a.x;
    oa.y = acc[1] + sn * bwa.y + b2a.y;
    oa.z = acc[2] + sn * bwa.z + b2a.z;
    oa.w = acc[3] + sn * bwa.w + b2a.w;
    ob.x = acc[4] + sn * bwb.x + b2b.x;
    ob.y = acc[5] + sn * bwb.y + b2b.y;
    ob.z = acc[6] + sn * bwb.z + b2b.z;
    ob.w = acc[7] + sn * bwb.w + b2b.w;
    float4* op = reinterpret_cast<float4*>(out + (size_t)row * FEAT + li * 8);
    op[0] = oa;
    op[1] = ob;
}

// ---------------------------------------------------------------------------
extern "C" void kernel_launch(void* const* d_in, const int* in_sizes, int n_in,
                              void* d_out, int out_size) {
    const float* x   = (const float*)d_in[0];
    const int*   ei  = (const int*)d_in[1];    // int64 downcast to int32 by harness
    const float* W1  = (const float*)d_in[2];
    const float* b1  = (const float*)d_in[3];
    const float* W2  = (const float*)d_in[4];
    const float* b2  = (const float*)d_in[5];
    float* out = (float*)d_out;

    int n = in_sizes[0] / INC;          // 100000
    int E = in_sizes[1] / 2;            // 3200000
    const int* srcp = ei;
    const int* dstp = ei + E;

    int nzb = (n + 255) / 256;          // zero blocks (391)
    int nsb = (INC + 1 + 3) / 4;        // small blocks (33)
    kA<<<nzb + nsb, 256>>>(W1, b1, W2, n, nzb);

    int nhb = (E + 255) / 256;          // histo blocks (12500)
    int ngb = (n + 7) / 8;              // gemm blocks  (12500)
    int gmax = (nhb > ngb) ? nhb : ngb;
    kB<<<2 * gmax, 256>>>(dstp, E, x, n, nhb, ngb);

    k_scan1<<<NBLK1, SB>>>(n);
    k_scan2<<<1, 512>>>();
    k_scan3<<<(n + 255) / 256, 256>>>(n);
    k_scatter<<<(E + 255) / 256, 256>>>(srcp, dstp, E);
    int pgrid = (n * 8 + 255) / 256;
    k_prop1<<<pgrid, 256>>>(n);
    k_prop2<<<pgrid, 256>>>(b2, out, n);
}